// round 5
// baseline (speedup 1.0000x reference)
#include <cuda_runtime.h>
#include <cstdint>

#define Tn 168
#define Pn 16
#define Hn 24
#define Gn 96
#define Bn 8192
#define GRP 14               // 16-lane groups per CTA
#define NTHREADS 224         // 7 warps
#define En 4                 // elements per group
#define EPC (GRP*En)         // 56
#define WS 100               // sWall row stride (floats): rows 20 apart -> +16 banks
#define VS 60                // sV row stride (floats): groups +16 banks, 16B aligned

// ---- packed f32x2 helpers ----
__device__ __forceinline__ unsigned long long pk2(float lo, float hi) {
    unsigned long long r;
    asm("mov.b64 %0, {%1, %2};" : "=l"(r) : "f"(lo), "f"(hi));
    return r;
}
__device__ __forceinline__ void fma2(unsigned long long& d, unsigned long long a, unsigned long long b) {
    asm("fma.rn.f32x2 %0, %1, %2, %0;" : "+l"(d) : "l"(a), "l"(b));
}
__device__ __forceinline__ void add2(unsigned long long& d, unsigned long long a) {
    asm("add.rn.f32x2 %0, %0, %1;" : "+l"(d) : "l"(a));
}
__device__ __forceinline__ void unpk2(unsigned long long v, float& lo, float& hi) {
    asm("mov.b64 {%0, %1}, %2;" : "=f"(lo), "=f"(hi) : "l"(v));
}
__device__ __forceinline__ float tanhapx(float x) {
    float y;
    asm("tanh.approx.f32 %0, %1;" : "=f"(y) : "f"(x));
    return y;
}

__global__ __launch_bounds__(NTHREADS, 1)
void lstm_fused_kernel(const float* __restrict__ x,
                       const float* __restrict__ Wih,   // [96,16]
                       const float* __restrict__ Whh,   // [96,24]
                       const float* __restrict__ bih,   // [96]
                       const float* __restrict__ bhh,   // [96]
                       const float* __restrict__ Wlin,  // [24,24]
                       const float* __restrict__ blin,  // [24]
                       float* __restrict__ out)         // [8192,24]
{
    // sWall rows: 0-15 = Wih (x rows), 16-39 = Whh (h rows).
    // Columns owner-major: gate (tt, unit j) -> col (j/3)*12 + tt*3 + j%3,
    // i/f/o rows pre-scaled by 0.5 (sigmoid(x) = 0.5*tanh(0.5x)+0.5).
    __shared__ float sWall[40 * WS];
    // sV per element: [0..15]=x bufA, [16..39]=h, [40..55]=x bufB
    __shared__ float sV[EPC * VS];
    __shared__ float sWlin[Hn * Hn];   // [j][m]
    __shared__ float sBlin[Hn];

    const int tid = threadIdx.x;
    const int g16 = tid >> 4;         // group 0..13 (2 per warp)
    const int l16 = tid & 15;
    const int kh  = l16 >> 3;         // row-half
    const int l8  = l16 & 7;          // gate owner (12 cols)
    const int el0 = g16 * En;
    const int eg0 = blockIdx.x * EPC + el0;
    const int j0  = l8 * 3;

    // ---- prologue ----
    for (int i = tid; i < Pn * Gn; i += NTHREADS) {
        int g = i >> 4, p = i & 15;
        int tt = g / Hn, j = g - tt * Hn;
        int own = (j / 3) * 12 + tt * 3 + (j % 3);
        float sc = (tt == 2) ? 1.0f : 0.5f;
        sWall[p * WS + own] = Wih[i] * sc;
    }
    for (int i = tid; i < Gn * Hn; i += NTHREADS) {
        int g = i / Hn, k = i - g * Hn;
        int tt = g / Hn, j = g - tt * Hn;
        int own = (j / 3) * 12 + tt * 3 + (j % 3);
        float sc = (tt == 2) ? 1.0f : 0.5f;
        sWall[(16 + k) * WS + own] = Whh[i] * sc;
    }
    for (int i = tid; i < Hn * Hn; i += NTHREADS) {
        int m = i / Hn, j = i - m * Hn;
        sWlin[j * Hn + m] = Wlin[i];
    }
    for (int i = tid; i < Hn; i += NTHREADS) sBlin[i] = blin[i];
    for (int i = tid; i < EPC * Hn; i += NTHREADS) {
        int e = i / Hn, u = i - e * Hn;
        sV[e * VS + 16 + u] = 0.0f;
    }

    // stage x(0) into bufA: lane covers (elem = l16>>2, quarter = l16&3)
    {
        int exl = (l16 >> 2);
        int q4  = (l16 & 3);
        int egx = eg0 + exl;
        if (egx < Bn) {
            float4 v = *reinterpret_cast<const float4*>(&x[(size_t)egx * (Tn * Pn) + q4 * 4]);
            *reinterpret_cast<float4*>(&sV[(el0 + exl) * VS + q4 * 4]) = v;
        }
    }

    // per-thread packed bias (kh==0 carries it)
    unsigned long long bias[6];
    {
        float bv[12];
#pragma unroll
        for (int q = 0; q < 12; q++) {
            int tt = q / 3;
            int g = tt * Hn + j0 + (q - tt * 3);
            float sc = (tt == 2) ? 1.0f : 0.5f;
            bv[q] = (kh == 0) ? (bih[g] + bhh[g]) * sc : 0.0f;
        }
#pragma unroll
        for (int s = 0; s < 6; s++) bias[s] = pk2(bv[2 * s], bv[2 * s + 1]);
    }
    __syncthreads();

    const float* vb0 = &sV[(el0 + 0) * VS];
    const float* vb1 = &sV[(el0 + 1) * VS];
    const float* vb2 = &sV[(el0 + 2) * VS];
    const float* vb3 = &sV[(el0 + 3) * VS];

    float c[2][3]    = {{0,0,0},{0,0,0}};
    float hown[2][3] = {{0,0,0},{0,0,0}};

    const int exl = (l16 >> 2);           // this lane's x-staging element
    const int q4  = (l16 & 3);
    const int egx = eg0 + exl;

    for (int t = 0; t < Tn; t++) {
        const int xbase = (t & 1) ? 40 : 0;
        const int xnext = 40 - xbase;

        // prefetch x(t+1)
        float4 xpf = make_float4(0.f, 0.f, 0.f, 0.f);
        if (t + 1 < Tn && egx < Bn)
            xpf = *reinterpret_cast<const float4*>(
                &x[(size_t)egx * (Tn * Pn) + (t + 1) * Pn + q4 * 4]);

        unsigned long long acc[En][6];
#pragma unroll
        for (int e = 0; e < En; e++)
#pragma unroll
            for (int s = 0; s < 6; s++) acc[e][s] = bias[s];

        const int vbA = kh ? 20 : xbase;   // v row base, loop A (16 rows)
        const int wbA = kh ? 20 : 0;       // w row base, loop A

#pragma unroll
        for (int blk = 0; blk < 4; blk++) {
            float4 v4[En];
            v4[0] = *reinterpret_cast<const float4*>(vb0 + vbA + blk * 4);
            v4[1] = *reinterpret_cast<const float4*>(vb1 + vbA + blk * 4);
            v4[2] = *reinterpret_cast<const float4*>(vb2 + vbA + blk * 4);
            v4[3] = *reinterpret_cast<const float4*>(vb3 + vbA + blk * 4);
#pragma unroll
            for (int r = 0; r < 4; r++) {
                const ulonglong2* wp = reinterpret_cast<const ulonglong2*>(
                    &sWall[(wbA + blk * 4 + r) * WS + l8 * 12]);
                ulonglong2 w0 = wp[0], w1 = wp[1], w2 = wp[2];
#pragma unroll
                for (int e = 0; e < En; e++) {
                    float vv = (r == 0) ? v4[e].x : (r == 1) ? v4[e].y : (r == 2) ? v4[e].z : v4[e].w;
                    unsigned long long vs = pk2(vv, vv);
                    fma2(acc[e][0], vs, w0.x);
                    fma2(acc[e][1], vs, w0.y);
                    fma2(acc[e][2], vs, w1.x);
                    fma2(acc[e][3], vs, w1.y);
                    fma2(acc[e][4], vs, w2.x);
                    fma2(acc[e][5], vs, w2.y);
                }
            }
        }
        // loop B (4 rows): kh=0 -> h units 0..3 (rows 16..19), kh=1 -> units 20..23 (rows 36..39)
        {
            const int bB = kh ? 36 : 16;
            float4 v4[En];
            v4[0] = *reinterpret_cast<const float4*>(vb0 + bB);
            v4[1] = *reinterpret_cast<const float4*>(vb1 + bB);
            v4[2] = *reinterpret_cast<const float4*>(vb2 + bB);
            v4[3] = *reinterpret_cast<const float4*>(vb3 + bB);
#pragma unroll
            for (int r = 0; r < 4; r++) {
                const ulonglong2* wp = reinterpret_cast<const ulonglong2*>(
                    &sWall[(bB + r) * WS + l8 * 12]);
                ulonglong2 w0 = wp[0], w1 = wp[1], w2 = wp[2];
#pragma unroll
                for (int e = 0; e < En; e++) {
                    float vv = (r == 0) ? v4[e].x : (r == 1) ? v4[e].y : (r == 2) ? v4[e].z : v4[e].w;
                    unsigned long long vs = pk2(vv, vv);
                    fma2(acc[e][0], vs, w0.x);
                    fma2(acc[e][1], vs, w0.y);
                    fma2(acc[e][2], vs, w1.x);
                    fma2(acc[e][3], vs, w1.y);
                    fma2(acc[e][4], vs, w2.x);
                    fma2(acc[e][5], vs, w2.y);
                }
            }
        }

        // cross-half reduction: xor over lane bit 3; both halves end with full sums
#pragma unroll
        for (int e = 0; e < En; e++)
#pragma unroll
            for (int s = 0; s < 6; s++) {
                unsigned long long o = __shfl_xor_sync(0xffffffffu, acc[e][s], 8);
                add2(acc[e][s], o);
            }

        // elementwise: kh half handles elems {2kh, 2kh+1}
#pragma unroll
        for (int ee = 0; ee < 2; ee++) {
            const int e = kh * 2 + ee;
            float v12[12];
#pragma unroll
            for (int s = 0; s < 6; s++) unpk2(acc[e][s], v12[2 * s], v12[2 * s + 1]);
#pragma unroll
            for (int q = 0; q < 3; q++) {
                float iv = fmaf(tanhapx(v12[q]),     0.5f, 0.5f);
                float fv = fmaf(tanhapx(v12[3 + q]), 0.5f, 0.5f);
                float gv = tanhapx(v12[6 + q]);
                float ov = fmaf(tanhapx(v12[9 + q]), 0.5f, 0.5f);
                c[ee][q] = fv * c[ee][q] + iv * gv;
                float hval = ov * tanhapx(c[ee][q]);
                hown[ee][q] = hval;
                sV[(el0 + e) * VS + 16 + j0 + q] = hval;
            }
        }

        // stage prefetched x into the other x buffer
        if (t + 1 < Tn && egx < Bn)
            *reinterpret_cast<float4*>(&sV[(el0 + exl) * VS + xnext + q4 * 4]) = xpf;

        __syncwarp();
    }

    // ---- epilogue: out = tanh(h_last) @ Wlin^T + blin ----
#pragma unroll
    for (int ee = 0; ee < 2; ee++) {
        const int e = kh * 2 + ee;
#pragma unroll
        for (int q = 0; q < 3; q++)
            sV[(el0 + e) * VS + 16 + j0 + q] = tanhapx(hown[ee][q]);
    }
    __syncwarp();

    {
        // 96 outputs per group over 16 lanes -> 6 each
#pragma unroll
        for (int q = 0; q < 6; q++) {
            int idx = l16 * 6 + q;           // 0..95
            int e   = idx / Hn;
            int m   = idx - e * Hn;
            int eg  = eg0 + e;
            float a = sBlin[m];
            const float* th = &sV[(el0 + e) * VS + 16];
#pragma unroll
            for (int j = 0; j < Hn; j++)
                a += th[j] * sWlin[j * Hn + m];
            if (eg < Bn) out[(size_t)eg * Hn + m] = a;
        }
    }
}

extern "C" void kernel_launch(void* const* d_in, const int* in_sizes, int n_in,
                              void* d_out, int out_size) {
    const float* x    = (const float*)d_in[0];
    const float* Wih  = (const float*)d_in[1];
    const float* Whh  = (const float*)d_in[2];
    const float* bih  = (const float*)d_in[3];
    const float* bhh  = (const float*)d_in[4];
    const float* Wlin = (const float*)d_in[5];
    const float* blin = (const float*)d_in[6];
    float* out = (float*)d_out;

    const int grid = (Bn + EPC - 1) / EPC;  // 147 -> 1 CTA per SM
    lstm_fused_kernel<<<grid, NTHREADS>>>(x, Wih, Whh, bih, bhh, Wlin, blin, out);
}